// round 5
// baseline (speedup 1.0000x reference)
#include <cuda_runtime.h>
#include <math.h>

#define NN 100000
#define EE 1600000
#define ENE (EE + NN)

// ---------------- scratch (device globals; no allocation allowed) ----------
__device__ float g_h[NN * 128];     // projected features of current layer
__device__ float g_x[NN * 128];     // activations (input to next layer)
__device__ float g_acc[NN * 128];   // aggregation accumulator
__device__ float g_als[NN * 4];     // per-node src attention logits
__device__ float g_ald[NN * 4];     // per-node dst attention logits
__device__ float g_emax[NN * 4];    // segment max
__device__ float g_den[NN * 4];     // segment sum -> inverse
__device__ float g_e[ENE * 4];      // per-edge scores / exp weights
__device__ int   g_src[ENE];        // decoded src indices (+self loops)
__device__ int   g_dst[ENE];        // decoded dst indices (+self loops)
__device__ int   g_is64;            // 1 if edge_index buffer is int64

// ---------------- helpers ---------------------------------------------------
__device__ __forceinline__ void atomicMaxF(float* addr, float v) {
    if (v >= 0.0f) atomicMax((int*)addr, __float_as_int(v));
    else           atomicMin((unsigned int*)addr, __float_as_uint(v));
}

__device__ __forceinline__ float lrelu(float v) { return v > 0.0f ? v : 0.2f * v; }

__device__ __forceinline__ void redAdd4(float* addr, float a, float b, float c, float d) {
    asm volatile("red.global.add.v4.f32 [%0], {%1, %2, %3, %4};"
                 :: "l"(addr), "f"(a), "f"(b), "f"(c), "f"(d) : "memory");
}

// ---------------- edge index dtype detection + decode ------------------------
// If buffer is int64 (all values < 2^32), odd 32-bit words are all zero.
// If int32, odd words are random node ids -> virtually never all zero.
__global__ void detect64(const unsigned int* __restrict__ w, int e) {
    if (threadIdx.x == 0 && blockIdx.x == 0) {
        int allz = 1;
        for (int k = 0; k < 64; k++) {
            long long idx = 2LL * (((long long)k * e) / 64) + 1;
            if (w[idx] != 0u) { allz = 0; break; }
        }
        g_is64 = allz;
    }
}

__global__ void decode_edges(const void* __restrict__ ei, int* __restrict__ src,
                             int* __restrict__ dst, int e, int n) {
    int i = blockIdx.x * blockDim.x + threadIdx.x;
    if (i >= e + n) return;
    if (i < e) {
        if (g_is64) {
            const long long* p = (const long long*)ei;
            src[i] = (int)p[i];
            dst[i] = (int)p[e + i];
        } else {
            const int* p = (const int*)ei;
            src[i] = p[i];
            dst[i] = p[e + i];
        }
    } else {
        src[i] = i - e;
        dst[i] = i - e;
    }
}

// ---------------- GEMM: H = X @ W  (X [n,128], W [128,128]) -----------------
__global__ void __launch_bounds__(256) gemm128(const float* __restrict__ X,
                                               const float* __restrict__ W,
                                               float* __restrict__ Hout, int n) {
    __shared__ float xs[64 * 128];   // 32 KB
    __shared__ float ws[32 * 128];   // 16 KB
    const int t  = threadIdx.x;
    const int tx = t & 31;
    const int ty = t >> 5;
    const int row0 = blockIdx.x * 64;

    for (int i = t; i < 64 * 32; i += 256) {
        int r = i >> 5;
        float4 v = make_float4(0.f, 0.f, 0.f, 0.f);
        if (row0 + r < n) v = ((const float4*)X)[(size_t)(row0 + r) * 32 + (i & 31)];
        ((float4*)xs)[i] = v;
    }

    float acc[8][4] = {};
    for (int kk = 0; kk < 128; kk += 32) {
        __syncthreads();
        for (int i = t; i < 32 * 32; i += 256)
            ((float4*)ws)[i] = ((const float4*)W)[kk * 32 + i];
        __syncthreads();
#pragma unroll
        for (int k = 0; k < 32; k++) {
            float4 w = ((float4*)ws)[k * 32 + tx];
#pragma unroll
            for (int r = 0; r < 8; r++) {
                float xv = xs[(ty * 8 + r) * 128 + kk + k];
                acc[r][0] += xv * w.x;
                acc[r][1] += xv * w.y;
                acc[r][2] += xv * w.z;
                acc[r][3] += xv * w.w;
            }
        }
    }
#pragma unroll
    for (int r = 0; r < 8; r++) {
        int row = row0 + ty * 8 + r;
        if (row < n)
            ((float4*)Hout)[(size_t)row * 32 + tx] =
                make_float4(acc[r][0], acc[r][1], acc[r][2], acc[r][3]);
    }
}

// ---------------- per-node attention logits (4 heads) -----------------------
__global__ void attn_scores(const float* __restrict__ Hm, const float* __restrict__ as,
                            const float* __restrict__ ad, float* __restrict__ als,
                            float* __restrict__ ald, int n) {
    int w = (blockIdx.x * blockDim.x + threadIdx.x) >> 5;
    int lane = threadIdx.x & 31;
    if (w >= n) return;
    float4 h4 = ((const float4*)Hm)[(size_t)w * 32 + lane];
    int head = lane >> 3;
    float4 a1 = ((const float4*)as)[head * 8 + (lane & 7)];
    float4 a2 = ((const float4*)ad)[head * 8 + (lane & 7)];
    float s = h4.x * a1.x + h4.y * a1.y + h4.z * a1.z + h4.w * a1.w;
    float d = h4.x * a2.x + h4.y * a2.y + h4.z * a2.z + h4.w * a2.w;
#pragma unroll
    for (int o = 4; o > 0; o >>= 1) {
        s += __shfl_down_sync(0xffffffffu, s, o);
        d += __shfl_down_sync(0xffffffffu, d, o);
    }
    if ((lane & 7) == 0) { als[w * 4 + head] = s; ald[w * 4 + head] = d; }
}

// ---------------- init: emax=-inf, den=0, acc=0 ------------------------------
__global__ void init_softmax(float* emax, float* den, float* acc, int nh, int nacc) {
    int i = blockIdx.x * blockDim.x + threadIdx.x;
    if (i < nh) { emax[i] = -INFINITY; den[i] = 0.f; }
    if (i < nacc) acc[i] = 0.f;
}

// ---------------- edge pass 1: scores + segment max (4 heads) ----------------
__global__ void edge_pass1(const int* __restrict__ src, const int* __restrict__ dst,
                           const float* __restrict__ als, const float* __restrict__ ald,
                           float* __restrict__ eo, float* emax, int tot) {
    int i = blockIdx.x * blockDim.x + threadIdx.x;
    if (i >= tot) return;
    int s = src[i], d = dst[i];
    float4 a = ((const float4*)als)[s];
    float4 b = ((const float4*)ald)[d];
    float4 ev;
    ev.x = lrelu(a.x + b.x);
    ev.y = lrelu(a.y + b.y);
    ev.z = lrelu(a.z + b.z);
    ev.w = lrelu(a.w + b.w);
    ((float4*)eo)[i] = ev;
    float* em = emax + (size_t)d * 4;
    atomicMaxF(em + 0, ev.x);
    atomicMaxF(em + 1, ev.y);
    atomicMaxF(em + 2, ev.z);
    atomicMaxF(em + 3, ev.w);
}

// ---------------- edge pass 2: exp + segment sum (4 heads) -------------------
__global__ void edge_pass2(const int* __restrict__ dst, float* __restrict__ eo,
                           const float* __restrict__ emax, float* den, int tot) {
    int i = blockIdx.x * blockDim.x + threadIdx.x;
    if (i >= tot) return;
    int d = dst[i];
    float4 ev = ((float4*)eo)[i];
    float4 mx = ((const float4*)emax)[d];
    float4 ee;
    ee.x = __expf(ev.x - mx.x);
    ee.y = __expf(ev.y - mx.y);
    ee.z = __expf(ev.z - mx.z);
    ee.w = __expf(ev.w - mx.w);
    ((float4*)eo)[i] = ee;
    redAdd4(den + (size_t)d * 4, ee.x, ee.y, ee.z, ee.w);
}

// ---------------- invert denominators ---------------------------------------
__global__ void invden_k(float* den, int tot) {
    int i = blockIdx.x * blockDim.x + threadIdx.x;
    if (i < tot) den[i] = 1.0f / (den[i] + 1e-16f);
}

// ---------------- edge aggregation: acc[dst] += h[src] * alpha ---------------
__global__ void edge_aggr(const int* __restrict__ src, const int* __restrict__ dst,
                          const float* __restrict__ eo, const float* __restrict__ invd,
                          const float* __restrict__ Hm, float* acc, int tot) {
    int w = (blockIdx.x * blockDim.x + threadIdx.x) >> 5;
    int lane = threadIdx.x & 31;
    if (w >= tot) return;
    int s = src[w], d = dst[w];
    int head = lane >> 3;
    float alpha = eo[(size_t)w * 4 + head] * invd[(size_t)d * 4 + head];
    float4 hv = ((const float4*)Hm)[(size_t)s * 32 + lane];
    redAdd4(acc + (size_t)d * 128 + lane * 4,
            hv.x * alpha, hv.y * alpha, hv.z * alpha, hv.w * alpha);
}

// ---------------- bias + batchnorm(eval) + ELU -------------------------------
__global__ void bn_elu(const float* __restrict__ acc, const float* __restrict__ b,
                       const float* __restrict__ gm, const float* __restrict__ be,
                       const float* __restrict__ mu, const float* __restrict__ var,
                       float* __restrict__ xo, int n) {
    int i = blockIdx.x * blockDim.x + threadIdx.x;
    if (i >= n * 128) return;
    int c = i & 127;
    float v = acc[i] + b[c];
    v = (v - mu[c]) * rsqrtf(var[c] + 1e-5f) * gm[c] + be[c];
    xo[i] = v > 0.f ? v : expm1f(v);
}

// ---------------- output layer: h2 = X @ W2 ([128,2]) + attn logits ----------
__global__ void gemm_out(const float* __restrict__ X, const float* __restrict__ W2,
                         const float* __restrict__ as2, const float* __restrict__ ad2,
                         float* __restrict__ h2, float* __restrict__ als,
                         float* __restrict__ ald, int n) {
    int w = (blockIdx.x * blockDim.x + threadIdx.x) >> 5;
    int lane = threadIdx.x & 31;
    if (w >= n) return;
    float4 x4 = ((const float4*)X)[(size_t)w * 32 + lane];
    float4 wa = ((const float4*)W2)[lane * 2];
    float4 wb = ((const float4*)W2)[lane * 2 + 1];
    float a0 = x4.x * wa.x + x4.y * wa.z + x4.z * wb.x + x4.w * wb.z;
    float a1 = x4.x * wa.y + x4.y * wa.w + x4.z * wb.y + x4.w * wb.w;
#pragma unroll
    for (int o = 16; o > 0; o >>= 1) {
        a0 += __shfl_down_sync(0xffffffffu, a0, o);
        a1 += __shfl_down_sync(0xffffffffu, a1, o);
    }
    if (lane == 0) {
        h2[w * 2]     = a0;
        h2[w * 2 + 1] = a1;
        als[w] = a0 * as2[0] + a1 * as2[1];
        ald[w] = a0 * ad2[0] + a1 * ad2[1];
    }
}

__global__ void init_out(float* emax, float* den, float* out, int n) {
    int i = blockIdx.x * blockDim.x + threadIdx.x;
    if (i < n) { emax[i] = -INFINITY; den[i] = 0.f; }
    if (i < 2 * n) out[i] = 0.f;
}

__global__ void edge_pass1o(const int* __restrict__ src, const int* __restrict__ dst,
                            const float* __restrict__ als, const float* __restrict__ ald,
                            float* __restrict__ eo, float* emax, int tot) {
    int i = blockIdx.x * blockDim.x + threadIdx.x;
    if (i >= tot) return;
    int s = src[i], d = dst[i];
    float ev = lrelu(als[s] + ald[d]);
    eo[i] = ev;
    atomicMaxF(&emax[d], ev);
}

__global__ void edge_pass2o(const int* __restrict__ dst, float* __restrict__ eo,
                            const float* __restrict__ emax, float* den, int tot) {
    int i = blockIdx.x * blockDim.x + threadIdx.x;
    if (i >= tot) return;
    int d = dst[i];
    float ee = __expf(eo[i] - emax[d]);
    eo[i] = ee;
    atomicAdd(&den[d], ee);
}

__global__ void edge_aggro(const int* __restrict__ src, const int* __restrict__ dst,
                           const float* __restrict__ eo, const float* __restrict__ invd,
                           const float* __restrict__ h2, float* out, int tot) {
    int i = blockIdx.x * blockDim.x + threadIdx.x;
    if (i >= tot) return;
    int s = src[i], d = dst[i];
    float alpha = eo[i] * invd[d];
    float h0 = h2[(size_t)s * 2], h1 = h2[(size_t)s * 2 + 1];
    asm volatile("red.global.add.v2.f32 [%0], {%1, %2};"
                 :: "l"(out + (size_t)d * 2), "f"(h0 * alpha), "f"(h1 * alpha) : "memory");
}

__global__ void bias_out(float* out, const float* __restrict__ b2, int n) {
    int i = blockIdx.x * blockDim.x + threadIdx.x;
    if (i < 2 * n) out[i] += b2[i & 1];
}

// ---------------- host ------------------------------------------------------
extern "C" void kernel_launch(void* const* d_in, const int* in_sizes, int n_in,
                              void* d_out, int out_size) {
    const float* x  = (const float*)d_in[0];
    const void*  ei = d_in[1];
    const float *W0 = (const float*)d_in[2],  *as0 = (const float*)d_in[3],
                *ad0 = (const float*)d_in[4], *b0 = (const float*)d_in[5],
                *gg0 = (const float*)d_in[6], *be0 = (const float*)d_in[7],
                *m0 = (const float*)d_in[8],  *v0 = (const float*)d_in[9];
    const float *W1 = (const float*)d_in[10], *as1 = (const float*)d_in[11],
                *ad1 = (const float*)d_in[12],*b1 = (const float*)d_in[13],
                *gg1 = (const float*)d_in[14],*be1 = (const float*)d_in[15],
                *m1 = (const float*)d_in[16], *v1 = (const float*)d_in[17];
    const float *W2 = (const float*)d_in[18], *as2 = (const float*)d_in[19],
                *ad2 = (const float*)d_in[20],*b2 = (const float*)d_in[21];
    float* out = (float*)d_out;

    const int n = in_sizes[0] / 128;
    const int e = in_sizes[1] / 2;
    const int tot = e + n;

    void* p;
    cudaGetSymbolAddress(&p, g_h);    float* hB    = (float*)p;
    cudaGetSymbolAddress(&p, g_x);    float* xB    = (float*)p;
    cudaGetSymbolAddress(&p, g_acc);  float* accB  = (float*)p;
    cudaGetSymbolAddress(&p, g_als);  float* alsB  = (float*)p;
    cudaGetSymbolAddress(&p, g_ald);  float* aldB  = (float*)p;
    cudaGetSymbolAddress(&p, g_emax); float* emaxB = (float*)p;
    cudaGetSymbolAddress(&p, g_den);  float* denB  = (float*)p;
    cudaGetSymbolAddress(&p, g_e);    float* eB    = (float*)p;
    cudaGetSymbolAddress(&p, g_src);  int*   srcB  = (int*)p;
    cudaGetSymbolAddress(&p, g_dst);  int*   dstB  = (int*)p;

    const int TB = 256;
    const int gGemm = (n + 63) / 64;
    const int gNodeW = (n + 7) / 8;
    const int gNC = (n * 128 + TB - 1) / TB;
    const int gEdge = (tot + TB - 1) / TB;
    const int gEdgeW = (tot + 7) / 8;

    // ---- decode edge indices (dtype-robust) ----
    detect64<<<1, 32>>>((const unsigned int*)ei, e);
    decode_edges<<<gEdge, TB>>>(ei, srcB, dstB, e, n);

    // ---- layer 0 ----
    gemm128<<<gGemm, TB>>>(x, W0, hB, n);
    attn_scores<<<gNodeW, TB>>>(hB, as0, ad0, alsB, aldB, n);
    init_softmax<<<gNC, TB>>>(emaxB, denB, accB, n * 4, n * 128);
    edge_pass1<<<gEdge, TB>>>(srcB, dstB, alsB, aldB, eB, emaxB, tot);
    edge_pass2<<<gEdge, TB>>>(dstB, eB, emaxB, denB, tot);
    invden_k<<<(n * 4 + TB - 1) / TB, TB>>>(denB, n * 4);
    edge_aggr<<<gEdgeW, TB>>>(srcB, dstB, eB, denB, hB, accB, tot);
    bn_elu<<<gNC, TB>>>(accB, b0, gg0, be0, m0, v0, xB, n);

    // ---- layer 1 ----
    gemm128<<<gGemm, TB>>>(xB, W1, hB, n);
    attn_scores<<<gNodeW, TB>>>(hB, as1, ad1, alsB, aldB, n);
    init_softmax<<<gNC, TB>>>(emaxB, denB, accB, n * 4, n * 128);
    edge_pass1<<<gEdge, TB>>>(srcB, dstB, alsB, aldB, eB, emaxB, tot);
    edge_pass2<<<gEdge, TB>>>(dstB, eB, emaxB, denB, tot);
    invden_k<<<(n * 4 + TB - 1) / TB, TB>>>(denB, n * 4);
    edge_aggr<<<gEdgeW, TB>>>(srcB, dstB, eB, denB, hB, accB, tot);
    bn_elu<<<gNC, TB>>>(accB, b1, gg1, be1, m1, v1, xB, n);

    // ---- layer 2 (heads=1, out=2) ----
    gemm_out<<<gNodeW, TB>>>(xB, W2, as2, ad2, hB, alsB, aldB, n);
    init_out<<<(2 * n + TB - 1) / TB, TB>>>(emaxB, denB, out, n);
    edge_pass1o<<<gEdge, TB>>>(srcB, dstB, alsB, aldB, eB, emaxB, tot);
    edge_pass2o<<<gEdge, TB>>>(dstB, eB, emaxB, denB, tot);
    invden_k<<<(n + TB - 1) / TB, TB>>>(denB, n);
    edge_aggro<<<gEdge, TB>>>(srcB, dstB, eB, denB, hB, out, tot);
    bias_out<<<(2 * n + TB - 1) / TB, TB>>>(out, b2, n);
}

// round 6
// speedup vs baseline: 1.1592x; 1.1592x over previous
#include <cuda_runtime.h>
#include <math.h>

#define NN 100000
#define EE 1600000
#define ENE (EE + NN)

// ---------------- scratch (device globals; no allocation allowed) ----------
__device__ float g_h[NN * 128];     // projected features of current layer
__device__ float g_x[NN * 128];     // activations (input to next layer)
__device__ float g_acc[NN * 128];   // unnormalized aggregation accumulator
__device__ float g_als[NN * 4];     // per-node src attention logits
__device__ float g_ald[NN * 4];     // per-node dst attention logits
__device__ float g_den[NN * 4];     // softmax denominators
__device__ int   g_src[ENE];        // decoded src indices (+self loops)
__device__ int   g_dst[ENE];        // decoded dst indices (+self loops)
__device__ int   g_is64;            // 1 if edge_index buffer is int64

// ---------------- helpers ---------------------------------------------------
__device__ __forceinline__ float lrelu(float v) { return v > 0.0f ? v : 0.2f * v; }

__device__ __forceinline__ void redAdd4(float* addr, float a, float b, float c, float d) {
    asm volatile("red.global.add.v4.f32 [%0], {%1, %2, %3, %4};"
                 :: "l"(addr), "f"(a), "f"(b), "f"(c), "f"(d) : "memory");
}

// ---------------- edge index dtype detection + decode ------------------------
__global__ void detect64(const unsigned int* __restrict__ w, int e) {
    if (threadIdx.x == 0 && blockIdx.x == 0) {
        int allz = 1;
        for (int k = 0; k < 64; k++) {
            long long idx = 2LL * (((long long)k * e) / 64) + 1;
            if (w[idx] != 0u) { allz = 0; break; }
        }
        g_is64 = allz;
    }
}

__global__ void decode_edges(const void* __restrict__ ei, int* __restrict__ src,
                             int* __restrict__ dst, int e, int n) {
    int i = blockIdx.x * blockDim.x + threadIdx.x;
    if (i >= e + n) return;
    if (i < e) {
        if (g_is64) {
            const long long* p = (const long long*)ei;
            src[i] = (int)p[i];
            dst[i] = (int)p[e + i];
        } else {
            const int* p = (const int*)ei;
            src[i] = p[i];
            dst[i] = p[e + i];
        }
    } else {
        src[i] = i - e;
        dst[i] = i - e;
    }
}

// ---------------- GEMM: H = X @ W, fused per-node attention logits -----------
// 256 threads, 64 rows/block, 8x4 register tile per thread.
// Epilogue: row-wise dot with a_src/a_dst, 8-lane segmented shuffle reduce.
__global__ void __launch_bounds__(256) gemm128(const float* __restrict__ X,
                                               const float* __restrict__ W,
                                               const float* __restrict__ as,
                                               const float* __restrict__ ad,
                                               float* __restrict__ Hout,
                                               float* __restrict__ als,
                                               float* __restrict__ ald, int n) {
    __shared__ float xs[64 * 128];   // 32 KB
    __shared__ float ws[32 * 128];   // 16 KB
    const int t  = threadIdx.x;
    const int tx = t & 31;
    const int ty = t >> 5;
    const int row0 = blockIdx.x * 64;

    for (int i = t; i < 64 * 32; i += 256) {
        int r = i >> 5;
        float4 v = make_float4(0.f, 0.f, 0.f, 0.f);
        if (row0 + r < n) v = ((const float4*)X)[(size_t)(row0 + r) * 32 + (i & 31)];
        ((float4*)xs)[i] = v;
    }

    float acc[8][4] = {};
    for (int kk = 0; kk < 128; kk += 32) {
        __syncthreads();
        for (int i = t; i < 32 * 32; i += 256)
            ((float4*)ws)[i] = ((const float4*)W)[kk * 32 + i];
        __syncthreads();
#pragma unroll
        for (int k = 0; k < 32; k++) {
            float4 w = ((float4*)ws)[k * 32 + tx];
#pragma unroll
            for (int r = 0; r < 8; r++) {
                float xv = xs[(ty * 8 + r) * 128 + kk + k];
                acc[r][0] += xv * w.x;
                acc[r][1] += xv * w.y;
                acc[r][2] += xv * w.z;
                acc[r][3] += xv * w.w;
            }
        }
    }
#pragma unroll
    for (int r = 0; r < 8; r++) {
        int row = row0 + ty * 8 + r;
        if (row < n)
            ((float4*)Hout)[(size_t)row * 32 + tx] =
                make_float4(acc[r][0], acc[r][1], acc[r][2], acc[r][3]);
    }

    // fused attention logits: head = tx>>3; lane's 4 cols are within one head
    const int head = tx >> 3;
    float4 a1 = ((const float4*)as)[head * 8 + (tx & 7)];
    float4 a2 = ((const float4*)ad)[head * 8 + (tx & 7)];
#pragma unroll
    for (int r = 0; r < 8; r++) {
        float s = acc[r][0] * a1.x + acc[r][1] * a1.y + acc[r][2] * a1.z + acc[r][3] * a1.w;
        float d = acc[r][0] * a2.x + acc[r][1] * a2.y + acc[r][2] * a2.z + acc[r][3] * a2.w;
#pragma unroll
        for (int o = 4; o > 0; o >>= 1) {
            s += __shfl_down_sync(0xffffffffu, s, o);
            d += __shfl_down_sync(0xffffffffu, d, o);
        }
        int row = row0 + ty * 8 + r;
        if ((tx & 7) == 0 && row < n) {
            als[row * 4 + head] = s;
            ald[row * 4 + head] = d;
        }
    }
}

// ---------------- init: den=0, acc=0 -----------------------------------------
__global__ void init_layer(float* den, float* acc, int nh, int nacc) {
    int i = blockIdx.x * blockDim.x + threadIdx.x;
    if (i < nh) den[i] = 0.f;
    if (i < nacc) acc[i] = 0.f;
}

// ---------------- fused edge pass: acc[dst]+=h[src]*exp(e), den[dst]+=exp(e) --
// one warp per edge; lane covers 4 channels of head lane>>3
__global__ void edge_fused(const int* __restrict__ src, const int* __restrict__ dst,
                           const float* __restrict__ als, const float* __restrict__ ald,
                           const float* __restrict__ Hm, float* acc, float* den, int tot) {
    int w = (blockIdx.x * blockDim.x + threadIdx.x) >> 5;
    int lane = threadIdx.x & 31;
    if (w >= tot) return;
    int s = src[w], d = dst[w];
    int head = lane >> 3;
    float ee = __expf(lrelu(als[s * 4 + head] + ald[d * 4 + head]));
    float4 hv = ((const float4*)Hm)[(size_t)s * 32 + lane];
    redAdd4(acc + (size_t)d * 128 + lane * 4,
            hv.x * ee, hv.y * ee, hv.z * ee, hv.w * ee);
    float e0 = __shfl_sync(0xffffffffu, ee, 0);
    float e1 = __shfl_sync(0xffffffffu, ee, 8);
    float e2 = __shfl_sync(0xffffffffu, ee, 16);
    float e3 = __shfl_sync(0xffffffffu, ee, 24);
    if (lane == 0) redAdd4(den + (size_t)d * 4, e0, e1, e2, e3);
}

// ---------------- normalize + bias + batchnorm(eval) + ELU -------------------
__global__ void bn_elu(const float* __restrict__ acc, const float* __restrict__ den,
                       const float* __restrict__ b, const float* __restrict__ gm,
                       const float* __restrict__ be, const float* __restrict__ mu,
                       const float* __restrict__ var, float* __restrict__ xo, int n) {
    int i = blockIdx.x * blockDim.x + threadIdx.x;
    if (i >= n * 128) return;
    int c = i & 127;
    int node = i >> 7;
    int head = c >> 5;
    float dn = den[node * 4 + head];
    float v = acc[i] / (dn + 1e-16f) + b[c];
    v = (v - mu[c]) * rsqrtf(var[c] + 1e-5f) * gm[c] + be[c];
    xo[i] = v > 0.f ? v : expm1f(v);
}

// ---------------- output layer: h2 = X @ W2 ([128,2]) + attn logits ----------
__global__ void gemm_out(const float* __restrict__ X, const float* __restrict__ W2,
                         const float* __restrict__ as2, const float* __restrict__ ad2,
                         float* __restrict__ h2, float* __restrict__ als,
                         float* __restrict__ ald, int n) {
    int w = (blockIdx.x * blockDim.x + threadIdx.x) >> 5;
    int lane = threadIdx.x & 31;
    if (w >= n) return;
    float4 x4 = ((const float4*)X)[(size_t)w * 32 + lane];
    float4 wa = ((const float4*)W2)[lane * 2];
    float4 wb = ((const float4*)W2)[lane * 2 + 1];
    float a0 = x4.x * wa.x + x4.y * wa.z + x4.z * wb.x + x4.w * wb.z;
    float a1 = x4.x * wa.y + x4.y * wa.w + x4.z * wb.y + x4.w * wb.w;
#pragma unroll
    for (int o = 16; o > 0; o >>= 1) {
        a0 += __shfl_down_sync(0xffffffffu, a0, o);
        a1 += __shfl_down_sync(0xffffffffu, a1, o);
    }
    if (lane == 0) {
        h2[w * 2]     = a0;
        h2[w * 2 + 1] = a1;
        als[w] = a0 * as2[0] + a1 * as2[1];
        ald[w] = a0 * ad2[0] + a1 * ad2[1];
    }
}

__global__ void init_out(float* den, float* acc2, int n) {
    int i = blockIdx.x * blockDim.x + threadIdx.x;
    if (i < n) den[i] = 0.f;
    if (i < 2 * n) acc2[i] = 0.f;
}

// fused layer-2 edge pass (thread per edge)
__global__ void edge_fused_out(const int* __restrict__ src, const int* __restrict__ dst,
                               const float* __restrict__ als, const float* __restrict__ ald,
                               const float* __restrict__ h2, float* acc2, float* den, int tot) {
    int i = blockIdx.x * blockDim.x + threadIdx.x;
    if (i >= tot) return;
    int s = src[i], d = dst[i];
    float ee = __expf(lrelu(als[s] + ald[d]));
    float h0 = h2[(size_t)s * 2], h1 = h2[(size_t)s * 2 + 1];
    asm volatile("red.global.add.v2.f32 [%0], {%1, %2};"
                 :: "l"(acc2 + (size_t)d * 2), "f"(h0 * ee), "f"(h1 * ee) : "memory");
    atomicAdd(&den[d], ee);
}

__global__ void finalize_out(const float* __restrict__ acc2, const float* __restrict__ den,
                             const float* __restrict__ b2, float* __restrict__ out, int n) {
    int i = blockIdx.x * blockDim.x + threadIdx.x;
    if (i >= 2 * n) return;
    out[i] = acc2[i] / (den[i >> 1] + 1e-16f) + b2[i & 1];
}

// ---------------- host ------------------------------------------------------
extern "C" void kernel_launch(void* const* d_in, const int* in_sizes, int n_in,
                              void* d_out, int out_size) {
    const float* x  = (const float*)d_in[0];
    const void*  ei = d_in[1];
    const float *W0 = (const float*)d_in[2],  *as0 = (const float*)d_in[3],
                *ad0 = (const float*)d_in[4], *b0 = (const float*)d_in[5],
                *gg0 = (const float*)d_in[6], *be0 = (const float*)d_in[7],
                *m0 = (const float*)d_in[8],  *v0 = (const float*)d_in[9];
    const float *W1 = (const float*)d_in[10], *as1 = (const float*)d_in[11],
                *ad1 = (const float*)d_in[12],*b1 = (const float*)d_in[13],
                *gg1 = (const float*)d_in[14],*be1 = (const float*)d_in[15],
                *m1 = (const float*)d_in[16], *v1 = (const float*)d_in[17];
    const float *W2 = (const float*)d_in[18], *as2 = (const float*)d_in[19],
                *ad2 = (const float*)d_in[20],*b2 = (const float*)d_in[21];
    float* out = (float*)d_out;

    const int n = in_sizes[0] / 128;
    const int e = in_sizes[1] / 2;
    const int tot = e + n;

    void* p;
    cudaGetSymbolAddress(&p, g_h);    float* hB    = (float*)p;
    cudaGetSymbolAddress(&p, g_x);    float* xB    = (float*)p;
    cudaGetSymbolAddress(&p, g_acc);  float* accB  = (float*)p;
    cudaGetSymbolAddress(&p, g_als);  float* alsB  = (float*)p;
    cudaGetSymbolAddress(&p, g_ald);  float* aldB  = (float*)p;
    cudaGetSymbolAddress(&p, g_den);  float* denB  = (float*)p;
    cudaGetSymbolAddress(&p, g_src);  int*   srcB  = (int*)p;
    cudaGetSymbolAddress(&p, g_dst);  int*   dstB  = (int*)p;

    const int TB = 256;
    const int gGemm  = (n + 63) / 64;
    const int gNodeW = (n + 7) / 8;
    const int gNC    = (n * 128 + TB - 1) / TB;
    const int gEdge  = (tot + TB - 1) / TB;
    const int gEdgeW = (tot + 7) / 8;

    // ---- decode edge indices (dtype-robust) ----
    detect64<<<1, 32>>>((const unsigned int*)ei, e);
    decode_edges<<<gEdge, TB>>>(ei, srcB, dstB, e, n);

    // ---- layer 0 ----
    gemm128<<<gGemm, TB>>>(x, W0, as0, ad0, hB, alsB, aldB, n);
    init_layer<<<gNC, TB>>>(denB, accB, n * 4, n * 128);
    edge_fused<<<gEdgeW, TB>>>(srcB, dstB, alsB, aldB, hB, accB, denB, tot);
    bn_elu<<<gNC, TB>>>(accB, denB, b0, gg0, be0, m0, v0, xB, n);

    // ---- layer 1 ----
    gemm128<<<gGemm, TB>>>(xB, W1, as1, ad1, hB, alsB, aldB, n);
    init_layer<<<gNC, TB>>>(denB, accB, n * 4, n * 128);
    edge_fused<<<gEdgeW, TB>>>(srcB, dstB, alsB, aldB, hB, accB, denB, tot);
    bn_elu<<<gNC, TB>>>(accB, denB, b1, gg1, be1, m1, v1, xB, n);

    // ---- layer 2 (heads=1, out=2) ----
    gemm_out<<<gNodeW, TB>>>(xB, W2, as2, ad2, hB, alsB, aldB, n);
    init_out<<<(2 * n + TB - 1) / TB, TB>>>(denB, accB, n);
    edge_fused_out<<<gEdge, TB>>>(srcB, dstB, alsB, aldB, hB, accB, denB, tot);
    finalize_out<<<(2 * n + TB - 1) / TB, TB>>>(accB, denB, b2, out, n);
}

// round 7
// speedup vs baseline: 2.3032x; 1.9868x over previous
#include <cuda_runtime.h>
#include <math.h>

#define NN 100000
#define EE 1600000
#define ENE (EE + NN)

// ---------------- scratch (device globals; no allocation allowed) ----------
__device__ float g_h[NN * 128];     // projected features of current layer
__device__ float g_x[NN * 128];     // activations (input to next layer)
__device__ float g_als[NN * 4];     // per-node src attention logits
__device__ float g_ald[NN * 4];     // per-node dst attention logits
__device__ int   g_src[ENE];        // decoded src indices (+self loops)
__device__ int   g_dst[ENE];        // decoded dst indices (+self loops)
__device__ int   g_csr[ENE];        // src indices sorted by dst
__device__ int   g_off[NN + 1];     // CSR row offsets (by dst)
__device__ int   g_deg[NN];         // degree count
__device__ int   g_incl[NN];        // block-inclusive scan scratch
__device__ int   g_woff[NN];        // scatter write cursors
__device__ int   g_bsum[512];       // block sums
__device__ int   g_is64;            // 1 if edge_index buffer is int64

// ---------------- helpers ---------------------------------------------------
__device__ __forceinline__ float lrelu(float v) { return v > 0.0f ? v : 0.2f * v; }

// ---------------- edge index dtype detection + decode ------------------------
__global__ void detect64(const unsigned int* __restrict__ w, int e) {
    if (threadIdx.x == 0 && blockIdx.x == 0) {
        int allz = 1;
        for (int k = 0; k < 64; k++) {
            long long idx = 2LL * (((long long)k * e) / 64) + 1;
            if (w[idx] != 0u) { allz = 0; break; }
        }
        g_is64 = allz;
    }
}

__global__ void decode_edges(const void* __restrict__ ei, int* __restrict__ src,
                             int* __restrict__ dst, int* __restrict__ deg, int e, int n) {
    int i = blockIdx.x * blockDim.x + threadIdx.x;
    if (i < n) deg[i] = 0;          // zero degree counters in the same sweep
    if (i >= e + n) return;
    if (i < e) {
        if (g_is64) {
            const long long* p = (const long long*)ei;
            src[i] = (int)p[i];
            dst[i] = (int)p[e + i];
        } else {
            const int* p = (const int*)ei;
            src[i] = p[i];
            dst[i] = p[e + i];
        }
    } else {
        src[i] = i - e;
        dst[i] = i - e;
    }
}

__global__ void count_deg(const int* __restrict__ dst, int* deg, int tot) {
    int i = blockIdx.x * blockDim.x + threadIdx.x;
    if (i < tot) atomicAdd(&deg[dst[i]], 1);
}

// block-inclusive scan (256/block) + block sums
__global__ void scan1(const int* __restrict__ deg, int* __restrict__ incl,
                      int* __restrict__ bsum, int n) {
    __shared__ int sm[256];
    int i = blockIdx.x * 256 + threadIdx.x;
    int v = (i < n) ? deg[i] : 0;
    sm[threadIdx.x] = v;
    __syncthreads();
#pragma unroll
    for (int o = 1; o < 256; o <<= 1) {
        int t = (threadIdx.x >= o) ? sm[threadIdx.x - o] : 0;
        __syncthreads();
        sm[threadIdx.x] += t;
        __syncthreads();
    }
    if (i < n) incl[i] = sm[threadIdx.x];
    if (threadIdx.x == 255) bsum[blockIdx.x] = sm[255];
}

// inclusive scan of block sums (nb <= 512), single block
__global__ void scan2(int* bsum, int nb) {
    __shared__ int sm[512];
    int t = threadIdx.x;
    sm[t] = (t < nb) ? bsum[t] : 0;
    __syncthreads();
#pragma unroll
    for (int o = 1; o < 512; o <<= 1) {
        int v = (t >= o) ? sm[t - o] : 0;
        __syncthreads();
        sm[t] += v;
        __syncthreads();
    }
    if (t < nb) bsum[t] = sm[t];
}

// exclusive offsets + write cursors
__global__ void scan3(const int* __restrict__ incl, const int* __restrict__ deg,
                      const int* __restrict__ bsum, int* __restrict__ off,
                      int* __restrict__ woff, int n, int tot) {
    int i = blockIdx.x * blockDim.x + threadIdx.x;
    if (i >= n) return;
    int b = i >> 8;
    int o = incl[i] - deg[i] + (b > 0 ? bsum[b - 1] : 0);
    off[i] = o;
    woff[i] = o;
    if (i == 0) off[n] = tot;
}

__global__ void scatter_csr(const int* __restrict__ src, const int* __restrict__ dst,
                            int* woff, int* __restrict__ csr, int tot) {
    int i = blockIdx.x * blockDim.x + threadIdx.x;
    if (i >= tot) return;
    int pos = atomicAdd(&woff[dst[i]], 1);
    csr[pos] = src[i];
}

// ---------------- GEMM: H = X @ W, fused per-node attention logits -----------
__global__ void __launch_bounds__(256) gemm128(const float* __restrict__ X,
                                               const float* __restrict__ W,
                                               const float* __restrict__ as,
                                               const float* __restrict__ ad,
                                               float* __restrict__ Hout,
                                               float* __restrict__ als,
                                               float* __restrict__ ald, int n) {
    __shared__ float xs[64 * 128];   // 32 KB
    __shared__ float ws[32 * 128];   // 16 KB
    const int t  = threadIdx.x;
    const int tx = t & 31;
    const int ty = t >> 5;
    const int row0 = blockIdx.x * 64;

    for (int i = t; i < 64 * 32; i += 256) {
        int r = i >> 5;
        float4 v = make_float4(0.f, 0.f, 0.f, 0.f);
        if (row0 + r < n) v = ((const float4*)X)[(size_t)(row0 + r) * 32 + (i & 31)];
        ((float4*)xs)[i] = v;
    }

    float acc[8][4] = {};
    for (int kk = 0; kk < 128; kk += 32) {
        __syncthreads();
        for (int i = t; i < 32 * 32; i += 256)
            ((float4*)ws)[i] = ((const float4*)W)[kk * 32 + i];
        __syncthreads();
#pragma unroll
        for (int k = 0; k < 32; k++) {
            float4 w = ((float4*)ws)[k * 32 + tx];
#pragma unroll
            for (int r = 0; r < 8; r++) {
                float xv = xs[(ty * 8 + r) * 128 + kk + k];
                acc[r][0] += xv * w.x;
                acc[r][1] += xv * w.y;
                acc[r][2] += xv * w.z;
                acc[r][3] += xv * w.w;
            }
        }
    }
#pragma unroll
    for (int r = 0; r < 8; r++) {
        int row = row0 + ty * 8 + r;
        if (row < n)
            ((float4*)Hout)[(size_t)row * 32 + tx] =
                make_float4(acc[r][0], acc[r][1], acc[r][2], acc[r][3]);
    }

    const int head = tx >> 3;
    float4 a1 = ((const float4*)as)[head * 8 + (tx & 7)];
    float4 a2 = ((const float4*)ad)[head * 8 + (tx & 7)];
#pragma unroll
    for (int r = 0; r < 8; r++) {
        float s = acc[r][0] * a1.x + acc[r][1] * a1.y + acc[r][2] * a1.z + acc[r][3] * a1.w;
        float d = acc[r][0] * a2.x + acc[r][1] * a2.y + acc[r][2] * a2.z + acc[r][3] * a2.w;
#pragma unroll
        for (int o = 4; o > 0; o >>= 1) {
            s += __shfl_down_sync(0xffffffffu, s, o);
            d += __shfl_down_sync(0xffffffffu, d, o);
        }
        int row = row0 + ty * 8 + r;
        if ((tx & 7) == 0 && row < n) {
            als[row * 4 + head] = s;
            ald[row * 4 + head] = d;
        }
    }
}

// ---------------- CSR aggregation + softmax + bias + BN + ELU (fused) --------
// one warp per dst node; lane owns 4 channels of head lane>>3; den is
// replicated across the 8 lanes of a head (no reduction needed).
__global__ void csr_layer(const int* __restrict__ off, const int* __restrict__ csr,
                          const float* __restrict__ als, const float* __restrict__ ald,
                          const float* __restrict__ Hm,
                          const float* __restrict__ b, const float* __restrict__ gm,
                          const float* __restrict__ be, const float* __restrict__ mu,
                          const float* __restrict__ var,
                          float* __restrict__ xo, int n) {
    int d = (blockIdx.x * blockDim.x + threadIdx.x) >> 5;
    int lane = threadIdx.x & 31;
    if (d >= n) return;
    const int head = lane >> 3;
    const int beg = off[d], end = off[d + 1];
    const float aldv = ald[d * 4 + head];

    float4 a = make_float4(0.f, 0.f, 0.f, 0.f);
    float den = 0.f;
    for (int j = beg; j < end; j++) {
        int s = csr[j];
        float ee = __expf(lrelu(als[s * 4 + head] + aldv));
        float4 hv = ((const float4*)Hm)[(size_t)s * 32 + lane];
        a.x += hv.x * ee;
        a.y += hv.y * ee;
        a.z += hv.z * ee;
        a.w += hv.w * ee;
        den += ee;
    }
    float inv = 1.0f / (den + 1e-16f);
    float4 b4  = ((const float4*)b)[lane];
    float4 gm4 = ((const float4*)gm)[lane];
    float4 be4 = ((const float4*)be)[lane];
    float4 mu4 = ((const float4*)mu)[lane];
    float4 v4  = ((const float4*)var)[lane];
    float4 o;
    float t;
    t = a.x * inv + b4.x; t = (t - mu4.x) * rsqrtf(v4.x + 1e-5f) * gm4.x + be4.x; o.x = t > 0.f ? t : expm1f(t);
    t = a.y * inv + b4.y; t = (t - mu4.y) * rsqrtf(v4.y + 1e-5f) * gm4.y + be4.y; o.y = t > 0.f ? t : expm1f(t);
    t = a.z * inv + b4.z; t = (t - mu4.z) * rsqrtf(v4.z + 1e-5f) * gm4.z + be4.z; o.z = t > 0.f ? t : expm1f(t);
    t = a.w * inv + b4.w; t = (t - mu4.w) * rsqrtf(v4.w + 1e-5f) * gm4.w + be4.w; o.w = t > 0.f ? t : expm1f(t);
    ((float4*)xo)[(size_t)d * 32 + lane] = o;
}

// ---------------- output layer: h2 = X @ W2 ([128,2]) + attn logits ----------
__global__ void gemm_out(const float* __restrict__ X, const float* __restrict__ W2,
                         const float* __restrict__ as2, const float* __restrict__ ad2,
                         float* __restrict__ h2, float* __restrict__ als,
                         float* __restrict__ ald, int n) {
    int w = (blockIdx.x * blockDim.x + threadIdx.x) >> 5;
    int lane = threadIdx.x & 31;
    if (w >= n) return;
    float4 x4 = ((const float4*)X)[(size_t)w * 32 + lane];
    float4 wa = ((const float4*)W2)[lane * 2];
    float4 wb = ((const float4*)W2)[lane * 2 + 1];
    float a0 = x4.x * wa.x + x4.y * wa.z + x4.z * wb.x + x4.w * wb.z;
    float a1 = x4.x * wa.y + x4.y * wa.w + x4.z * wb.y + x4.w * wb.w;
#pragma unroll
    for (int o = 16; o > 0; o >>= 1) {
        a0 += __shfl_down_sync(0xffffffffu, a0, o);
        a1 += __shfl_down_sync(0xffffffffu, a1, o);
    }
    if (lane == 0) {
        h2[w * 2]     = a0;
        h2[w * 2 + 1] = a1;
        als[w] = a0 * as2[0] + a1 * as2[1];
        ald[w] = a0 * ad2[0] + a1 * ad2[1];
    }
}

// ---------------- CSR output aggregation (warp per dst, lanes over edges) ----
__global__ void csr_out(const int* __restrict__ off, const int* __restrict__ csr,
                        const float* __restrict__ als, const float* __restrict__ ald,
                        const float* __restrict__ h2, const float* __restrict__ b2,
                        float* __restrict__ out, int n) {
    int d = (blockIdx.x * blockDim.x + threadIdx.x) >> 5;
    int lane = threadIdx.x & 31;
    if (d >= n) return;
    const int beg = off[d], end = off[d + 1];
    const float aldv = ald[d];
    float a0 = 0.f, a1 = 0.f, den = 0.f;
    for (int j = beg + lane; j < end; j += 32) {
        int s = csr[j];
        float ee = __expf(lrelu(als[s] + aldv));
        float2 hv = ((const float2*)h2)[s];
        a0 += hv.x * ee;
        a1 += hv.y * ee;
        den += ee;
    }
#pragma unroll
    for (int o = 16; o > 0; o >>= 1) {
        a0  += __shfl_down_sync(0xffffffffu, a0, o);
        a1  += __shfl_down_sync(0xffffffffu, a1, o);
        den += __shfl_down_sync(0xffffffffu, den, o);
    }
    if (lane == 0) {
        float inv = 1.0f / (den + 1e-16f);
        out[d * 2]     = a0 * inv + b2[0];
        out[d * 2 + 1] = a1 * inv + b2[1];
    }
}

// ---------------- host ------------------------------------------------------
extern "C" void kernel_launch(void* const* d_in, const int* in_sizes, int n_in,
                              void* d_out, int out_size) {
    const float* x  = (const float*)d_in[0];
    const void*  ei = d_in[1];
    const float *W0 = (const float*)d_in[2],  *as0 = (const float*)d_in[3],
                *ad0 = (const float*)d_in[4], *b0 = (const float*)d_in[5],
                *gg0 = (const float*)d_in[6], *be0 = (const float*)d_in[7],
                *m0 = (const float*)d_in[8],  *v0 = (const float*)d_in[9];
    const float *W1 = (const float*)d_in[10], *as1 = (const float*)d_in[11],
                *ad1 = (const float*)d_in[12],*b1 = (const float*)d_in[13],
                *gg1 = (const float*)d_in[14],*be1 = (const float*)d_in[15],
                *m1 = (const float*)d_in[16], *v1 = (const float*)d_in[17];
    const float *W2 = (const float*)d_in[18], *as2 = (const float*)d_in[19],
                *ad2 = (const float*)d_in[20],*b2 = (const float*)d_in[21];
    float* out = (float*)d_out;

    const int n = in_sizes[0] / 128;
    const int e = in_sizes[1] / 2;
    const int tot = e + n;

    void* p;
    cudaGetSymbolAddress(&p, g_h);    float* hB    = (float*)p;
    cudaGetSymbolAddress(&p, g_x);    float* xB    = (float*)p;
    cudaGetSymbolAddress(&p, g_als);  float* alsB  = (float*)p;
    cudaGetSymbolAddress(&p, g_ald);  float* aldB  = (float*)p;
    cudaGetSymbolAddress(&p, g_src);  int*   srcB  = (int*)p;
    cudaGetSymbolAddress(&p, g_dst);  int*   dstB  = (int*)p;
    cudaGetSymbolAddress(&p, g_csr);  int*   csrB  = (int*)p;
    cudaGetSymbolAddress(&p, g_off);  int*   offB  = (int*)p;
    cudaGetSymbolAddress(&p, g_deg);  int*   degB  = (int*)p;
    cudaGetSymbolAddress(&p, g_incl); int*   inclB = (int*)p;
    cudaGetSymbolAddress(&p, g_woff); int*   woffB = (int*)p;
    cudaGetSymbolAddress(&p, g_bsum); int*   bsumB = (int*)p;

    const int TB = 256;
    const int gGemm  = (n + 63) / 64;
    const int gNodeW = (n + 7) / 8;
    const int gEdge  = (tot + TB - 1) / TB;
    const int gScan  = (n + 255) / 256;

    // ---- decode + CSR build (once; reused by all 3 layers) ----
    detect64<<<1, 32>>>((const unsigned int*)ei, e);
    decode_edges<<<gEdge, TB>>>(ei, srcB, dstB, degB, e, n);
    count_deg<<<gEdge, TB>>>(dstB, degB, tot);
    scan1<<<gScan, 256>>>(degB, inclB, bsumB, n);
    scan2<<<1, 512>>>(bsumB, gScan);
    scan3<<<gScan, 256>>>(inclB, degB, bsumB, offB, woffB, n, tot);
    scatter_csr<<<gEdge, TB>>>(srcB, dstB, woffB, csrB, tot);

    // ---- layer 0 ----
    gemm128<<<gGemm, TB>>>(x, W0, as0, ad0, hB, alsB, aldB, n);
    csr_layer<<<gNodeW, TB>>>(offB, csrB, alsB, aldB, hB, b0, gg0, be0, m0, v0, xB, n);

    // ---- layer 1 ----
    gemm128<<<gGemm, TB>>>(xB, W1, as1, ad1, hB, alsB, aldB, n);
    csr_layer<<<gNodeW, TB>>>(offB, csrB, alsB, aldB, hB, b1, gg1, be1, m1, v1, xB, n);

    // ---- layer 2 (heads=1, out=2) ----
    gemm_out<<<gNodeW, TB>>>(xB, W2, as2, ad2, hB, alsB, aldB, n);
    csr_out<<<gNodeW, TB>>>(offB, csrB, alsB, aldB, hB, b2, out, n);
}